// round 1
// baseline (speedup 1.0000x reference)
#include <cuda_runtime.h>

// InfoEnlargeEmbedding: out[b,l,:] = concat(x[b,l,:], x[b,idxs[b,0],:], x[b,idxs[b,1],:])
// B=64, L=1024, D=256, K=2. Output row = 768 floats = 192 float4.
// Pure HBM-streaming kernel: 64 MiB read + 192 MiB write; gather rows are L2-resident.

static constexpr int B = 64;
static constexpr int L = 1024;
static constexpr int D = 256;       // floats
static constexpr int D4 = D / 4;    // 64 float4 per source row
static constexpr int K = 2;
static constexpr int OUT4 = D4 * (1 + K);  // 192 float4 per output row

__global__ void __launch_bounds__(OUT4)
info_enlarge_kernel(const float4* __restrict__ x,
                    const int* __restrict__ idxs,
                    float4* __restrict__ out) {
    const int bl = blockIdx.x;          // b*L + l, 0..65535
    const int b  = bl >> 10;            // / L
    const int c  = threadIdx.x;         // 0..191 (float4 index within output row)

    const float4* src;
    if (c < D4) {
        // straight copy of x[b, l, :]
        src = x + (size_t)bl * D4 + c;
    } else {
        // broadcast gather of x[b, idxs[b,k], :]  (L2-resident after first l)
        const int kd = c - D4;
        const int k  = kd >> 6;         // / D4
        const int dd = kd & (D4 - 1);
        const int li = __ldg(idxs + b * K + k);
        src = x + ((size_t)b * L + li) * D4 + dd;
    }
    out[(size_t)bl * OUT4 + c] = __ldg(src);
}

extern "C" void kernel_launch(void* const* d_in, const int* in_sizes, int n_in,
                              void* d_out, int out_size) {
    const float4* x  = (const float4*)d_in[0];
    const int* idxs  = (const int*)d_in[1];
    float4* out      = (float4*)d_out;

    info_enlarge_kernel<<<B * L, OUT4>>>(x, idxs, out);
}

// round 2
// speedup vs baseline: 1.1476x; 1.1476x over previous
#include <cuda_runtime.h>

// InfoEnlargeEmbedding: out[b,l,:] = concat(x[b,l,:], x[b,idxs[b,0],:], x[b,idxs[b,1],:])
// B=64, L=1024, D=256, K=2.
// R2: 8 rows per block. Copy threads batch 8 independent LDGs (MLP=8);
// gather threads load once and store 8x. Streaming hints on stores.

static constexpr int B = 64;
static constexpr int L = 1024;
static constexpr int D = 256;       // floats
static constexpr int D4 = D / 4;    // 64 float4 per source row
static constexpr int K = 2;
static constexpr int OUT4 = D4 * (1 + K);  // 192 float4 per output row
static constexpr int R = 8;         // rows (bl) per block

__global__ void __launch_bounds__(OUT4)
info_enlarge_kernel(const float4* __restrict__ x,
                    const int* __restrict__ idxs,
                    float4* __restrict__ out) {
    const int row0 = blockIdx.x * R;    // base bl; all R rows share the same b
    const int b    = row0 >> 10;        // / L  (L=1024, R divides 1024)
    const int c    = threadIdx.x;       // 0..191

    if (c < D4) {
        // Straight copy region: 8 independent loads, then 8 stores.
        float4 v[R];
        #pragma unroll
        for (int u = 0; u < R; u++)
            v[u] = __ldcs(x + (size_t)(row0 + u) * D4 + c);
        #pragma unroll
        for (int u = 0; u < R; u++)
            __stcs(out + (size_t)(row0 + u) * OUT4 + c, v[u]);
    } else {
        // Gather region: same source row for all 8 output rows -> load once, store 8x.
        const int kd = c - D4;
        const int k  = kd >> 6;          // / D4
        const int dd = kd & (D4 - 1);
        const int li = __ldg(idxs + b * K + k);
        const float4 v = __ldg(x + ((size_t)b * L + li) * D4 + dd);
        #pragma unroll
        for (int u = 0; u < R; u++)
            __stcs(out + (size_t)(row0 + u) * OUT4 + c, v);
    }
}

extern "C" void kernel_launch(void* const* d_in, const int* in_sizes, int n_in,
                              void* d_out, int out_size) {
    const float4* x  = (const float4*)d_in[0];
    const int* idxs  = (const int*)d_in[1];
    float4* out      = (float4*)d_out;

    info_enlarge_kernel<<<(B * L) / R, OUT4>>>(x, idxs, out);
}